// round 9
// baseline (speedup 1.0000x reference)
#include <cuda_runtime.h>
#include <cstdint>

// Problem constants
#define Lnum 3
#define Bsz  512
#define Hd   1024
#define TAUn 96
#define Tt   8

#define GRID 256
#define NTH  256

// SMEM layout (byte offsets)
// 4 stages x (A 9216 + B 18432) = 110592 ; gates ALIASED onto stage region
#define STG   27648
#define ST_A(buf) ((buf) * STG)
#define ST_B(buf) ((buf) * STG + 9216)
#define OFF_GATES 0          // alias: gates live in stage region (dead at epilogue)
#define OFF_BIAS  110592     // 1536
#define SMEM_DYN  112128

#define APITCH 36            // floats per staged row (32 data + 4 pad)
#define GPITCH 36
#define GSTRIDE (64 * GPITCH)    // 2304 floats per gate (64 rows)

// Persistent device state (canonical layouts only)
__device__ __align__(16) float g_wT[(size_t)2 * Lnum * 4096 * 1024]; // rounded [Wih; Whh]
__device__ __align__(16) float g_h[(size_t)2 * Lnum * Bsz * Hd];     // ping-pong hidden (rounded)
__device__ __align__(16) float g_y[(size_t)TAUn * Bsz * Hd];         // exact step outputs
__device__ unsigned int g_bar;                                       // ticket barrier

// ---------------------------------------------------------------- helpers
__device__ __forceinline__ uint32_t smem_u32(const void* p) {
    uint32_t a;
    asm("{ .reg .u64 t; cvta.to.shared.u64 t, %1; cvt.u32.u64 %0, t; }" : "=r"(a) : "l"(p));
    return a;
}
__device__ __forceinline__ float tf32r(float x) {
    uint32_t u;
    asm("cvt.rna.tf32.f32 %0, %1;" : "=r"(u) : "f"(x));
    return __uint_as_float(u);
}
__device__ __forceinline__ float4 cvt4(float4 v) {
    v.x = tf32r(v.x); v.y = tf32r(v.y); v.z = tf32r(v.z); v.w = tf32r(v.w);
    return v;
}
__device__ __forceinline__ float sigmoidf_(float x) { return 1.0f / (1.0f + __expf(-x)); }
__device__ __forceinline__ float tanhf_(float x) {
    float e = __expf(2.0f * x);
    return 1.0f - 2.0f / (e + 1.0f);
}

#define CP16(dst32, src) \
    asm volatile("cp.async.cg.shared.global [%0], [%1], 16;" :: "r"(dst32), "l"(src) : "memory")
#define CP_COMMIT()  asm volatile("cp.async.commit_group;" ::: "memory")
#define CP_WAIT2()   asm volatile("cp.async.wait_group 2;" ::: "memory")

__device__ __forceinline__ void mma_tf32(float& d0, float& d1, float& d2, float& d3,
                                         float a0, float a1, float a2, float a3,
                                         float b0, float b1) {
    asm volatile("mma.sync.aligned.m16n8k8.row.col.f32.tf32.tf32.f32 "
                 "{%0,%1,%2,%3}, {%4,%5,%6,%7}, {%8,%9}, {%0,%1,%2,%3};"
                 : "+f"(d0), "+f"(d1), "+f"(d2), "+f"(d3)
                 : "r"(__float_as_uint(a0)), "r"(__float_as_uint(a1)),
                   "r"(__float_as_uint(a2)), "r"(__float_as_uint(a3)),
                   "r"(__float_as_uint(b0)), "r"(__float_as_uint(b1)));
}

__device__ __forceinline__ void grid_sync() {
    __syncthreads();
    if (threadIdx.x == 0) {
        __threadfence();
        unsigned int ticket = atomicAdd(&g_bar, 1u);
        unsigned int target = ticket - (ticket % GRID) + GRID;
        volatile unsigned int* p = &g_bar;
        while ((int)(*p - target) < 0) { }
        __threadfence();
    }
    __syncthreads();
}

// ---------------------------------------------------------------- kernel
__global__ void __launch_bounds__(NTH, 2)
deepar_mma(const float* __restrict__ hidden,
           const float* __restrict__ cell,
           const float* __restrict__ W_ih,
           const float* __restrict__ W_hh,
           const float* __restrict__ b_ih,
           const float* __restrict__ b_hh,
           const float* __restrict__ W1,
           const float* __restrict__ b1,
           const float* __restrict__ W2,
           const float* __restrict__ b2,
           float* __restrict__ out)
{
    extern __shared__ __align__(16) char smb[];
    const uint32_t sb32 = smem_u32(smb);

    const int tid  = threadIdx.x;
    const int w    = tid >> 5;          // 0..7
    const int lane = tid & 31;
    const int wm   = w >> 2;            // 0..1  (M 32-row slice)
    const int wn   = w & 3;             // 0..3  (gate)
    const int g_   = lane >> 2;         // groupID
    const int t_   = lane & 3;          // threadID_in_group
    const int bt = blockIdx.x >> 5;     // 0..7  batch tile (64 rows)
    const int nt = blockIdx.x & 31;     // 0..31 hidden tile (32 cols)
    const int b0 = bt * 64;
    const int j0 = nt * 32;

    float* gatesS = (float*)(smb + OFF_GATES);   // aliased on stage region
    float* biasS  = (float*)(smb + OFF_BIAS);

    // ================= one-time precompute (elementwise only) =================
    {
        const int gt = blockIdx.x * NTH + tid;
        const float4* s1 = (const float4*)W_ih;
        const float4* s2 = (const float4*)W_hh;
        float4* d = (float4*)g_wT;
        const int PER = 3 * 4096 * 256;          // float4 per weight tensor
        for (int v = gt; v < PER; v += GRID * NTH) {
            d[v]       = cvt4(s1[v]);
            d[v + PER] = cvt4(s2[v]);
        }
        const float4* hs = (const float4*)hidden;
        float4* hd = (float4*)g_h;               // ping 0
        const int PH = 3 * 512 * 256;
        for (int v = gt; v < PH; v += GRID * NTH)
            hd[v] = cvt4(hs[v]);
    }

    // per-CTA bias (exact fp32): biasS[l*128 + g*32 + jj]
    for (int idx = tid; idx < Lnum * 128; idx += NTH) {
        const int l = idx >> 7, r = idx & 127;
        const int gi = l * 4096 + ((r >> 5) << 10) + j0 + (r & 31);
        biasS[idx] = b_ih[gi] + b_hh[gi];
    }

    // per-thread cell state in registers: thread owns (m = tid>>2, 8 j's)
    const int ml = tid >> 2;            // 0..63
    const int jb8 = (tid & 3) << 3;     // 0,8,16,24
    float creg[Lnum][8];
    #pragma unroll
    for (int l = 0; l < Lnum; l++) {
        #pragma unroll
        for (int q4 = 0; q4 < 2; q4++) {
            float4 v = *(const float4*)&cell[((size_t)(l * Bsz + b0 + ml) << 10)
                                             + j0 + jb8 + q4 * 4];
            creg[l][q4 * 4 + 0] = v.x; creg[l][q4 * 4 + 1] = v.y;
            creg[l][q4 * 4 + 2] = v.z; creg[l][q4 * 4 + 3] = v.w;
        }
    }
    grid_sync();

    const uint32_t stage0 = sb32;

    // ================= main recurrence =================
    for (int t = 0; t < TAUn; t++) {
        const int p  = t & 1;
        const int np = 1 - p;
        #pragma unroll
        for (int l = 0; l < Lnum; l++) {
            // canonical A sources: [512 rows][1024 cols]
            const float* Xp = (l == 0)
                ? g_h + (((size_t)(p * 3 + 2) * Bsz) << 10)
                : g_h + (((size_t)(np * 3 + (l - 1)) * Bsz) << 10);
            const float* Hp = g_h + (((size_t)(p * 3 + l) * Bsz) << 10);
            const float* Wi = g_wT + ((size_t)l << 22);                      // l*4096*1024
            const float* Wh = g_wT + ((size_t)(3 + l) << 22);

            float acc[2][4][4];
            #pragma unroll
            for (int mt = 0; mt < 2; mt++)
                #pragma unroll
                for (int jb = 0; jb < 4; jb++)
                    #pragma unroll
                    for (int r = 0; r < 4; r++) acc[mt][jb][r] = 0.0f;

// Staging per stage: A 512 CP16 (8KB, 64 rows), B 1024 CP16 (16KB, 128 rows).
#define ISSUE(c_, buf_) do {                                                   \
            const int cc_ = (c_);                                              \
            const float* Ap_ = (cc_ < 32) ? Xp : Hp;                           \
            const float* Wp_ = (cc_ < 32) ? Wi : Wh;                           \
            const int kc_ = (cc_ & 31) * 32;                                   \
            const uint32_t dA_ = stage0 + ST_A(buf_);                          \
            const uint32_t dB_ = stage0 + ST_B(buf_);                          \
            _Pragma("unroll")                                                  \
            for (int h_ = 0; h_ < 2; h_++) {                                   \
                const int cid_ = tid + h_ * NTH;                               \
                const int row_ = cid_ >> 3, k4_ = cid_ & 7;                    \
                CP16(dA_ + row_ * 144 + k4_ * 16,                              \
                     Ap_ + ((size_t)(b0 + row_) << 10) + kc_ + k4_ * 4);       \
            }                                                                  \
            _Pragma("unroll")                                                  \
            for (int h_ = 0; h_ < 4; h_++) {                                   \
                const int cid_ = tid + h_ * NTH;                               \
                const int row_ = cid_ >> 3, k4_ = cid_ & 7;                    \
                const int gg_ = row_ >> 5, jj_ = row_ & 31;                    \
                CP16(dB_ + row_ * 144 + k4_ * 16,                              \
                     Wp_ + ((size_t)(gg_ * 1024 + j0 + jj_) << 10) + kc_ + k4_ * 4); \
            } } while (0)

            ISSUE(0, 0); CP_COMMIT();
            ISSUE(1, 1); CP_COMMIT();
            ISSUE(2, 2); CP_COMMIT();

            #pragma unroll 1
            for (int s = 0; s < 64; s++) {
                const int buf = s & 3;
                CP_WAIT2();
                __syncthreads();
                if (s + 3 < 64) { ISSUE(s + 3, (s + 3) & 3); }
                CP_COMMIT();   // dummy when nothing issued: keeps wait count exact

                const float* As = (const float*)(smb + ST_A(buf));
                const float* Bs = (const float*)(smb + ST_B(buf));
                #pragma unroll
                for (int ks = 0; ks < 4; ks++) {
                    float a[2][4];
                    #pragma unroll
                    for (int mt = 0; mt < 2; mt++) {
                        const float* Ar = As + (wm * 32 + mt * 16) * APITCH + ks * 8;
                        a[mt][0] = Ar[g_ * APITCH + t_];
                        a[mt][1] = Ar[(g_ + 8) * APITCH + t_];
                        a[mt][2] = Ar[g_ * APITCH + t_ + 4];
                        a[mt][3] = Ar[(g_ + 8) * APITCH + t_ + 4];
                    }
                    float b[4][2];
                    #pragma unroll
                    for (int jb = 0; jb < 4; jb++) {
                        const float* Br = Bs + (wn * 32 + jb * 8 + g_) * APITCH
                                        + ks * 8 + t_;
                        b[jb][0] = Br[0];
                        b[jb][1] = Br[4];
                    }
                    #pragma unroll
                    for (int mt = 0; mt < 2; mt++)
                        #pragma unroll
                        for (int jb = 0; jb < 4; jb++)
                            mma_tf32(acc[mt][jb][0], acc[mt][jb][1],
                                     acc[mt][jb][2], acc[mt][jb][3],
                                     a[mt][0], a[mt][1], a[mt][2], a[mt][3],
                                     b[jb][0], b[jb][1]);
                }
            }
#undef ISSUE

            // ---- epilogue: accums -> smem gate buffer (aliases stage region) ----
            __syncthreads();
            #pragma unroll
            for (int mt = 0; mt < 2; mt++) {
                const int mb2 = wm * 32 + mt * 16 + g_;
                #pragma unroll
                for (int jb = 0; jb < 4; jb++) {
                    const int jc = jb * 8 + (t_ << 1);
                    float* gp = gatesS + wn * GSTRIDE + mb2 * GPITCH + jc;
                    *(float2*)gp = make_float2(acc[mt][jb][0], acc[mt][jb][1]);
                    *(float2*)(gp + 8 * GPITCH) = make_float2(acc[mt][jb][2], acc[mt][jb][3]);
                }
            }
            __syncthreads();

            // ---- LSTM cell (thread owns (ml, jb8..+8)) ----
            float G[4][8];
            #pragma unroll
            for (int g = 0; g < 4; g++)
                #pragma unroll
                for (int q4 = 0; q4 < 2; q4++) {
                    float4 v = *(const float4*)(gatesS + g * GSTRIDE + ml * GPITCH
                                                + jb8 + q4 * 4);
                    G[g][q4 * 4 + 0] = v.x; G[g][q4 * 4 + 1] = v.y;
                    G[g][q4 * 4 + 2] = v.z; G[g][q4 * 4 + 3] = v.w;
                }
            float hn[8];
            #pragma unroll
            for (int q = 0; q < 8; q++) {
                const int bb = l * 128 + jb8 + q;
                const float gi = sigmoidf_(G[0][q] + biasS[bb]);
                const float gf = sigmoidf_(G[1][q] + biasS[bb + 32]);
                const float gg = tanhf_  (G[2][q] + biasS[bb + 64]);
                const float go = sigmoidf_(G[3][q] + biasS[bb + 96]);
                const float cn = gf * creg[l][q] + gi * gg;
                creg[l][q] = cn;
                hn[q] = go * tanhf_(cn);
            }
            if (l == Lnum - 1) {
                float* yb = g_y + (((size_t)t * Bsz + b0 + ml) << 10) + j0 + jb8;
                #pragma unroll
                for (int q4 = 0; q4 < 2; q4++)
                    *(float4*)(yb + q4 * 4) = make_float4(hn[q4*4], hn[q4*4+1],
                                                          hn[q4*4+2], hn[q4*4+3]);
            }
            // rounded h -> canonical g_h[np][l]
            {
                float* hb = g_h + (((size_t)(np * 3 + l) * Bsz + b0 + ml) << 10)
                          + j0 + jb8;
                #pragma unroll
                for (int q4 = 0; q4 < 2; q4++) {
                    float4 v;
                    v.x = tf32r(hn[q4 * 4 + 0]); v.y = tf32r(hn[q4 * 4 + 1]);
                    v.z = tf32r(hn[q4 * 4 + 2]); v.w = tf32r(hn[q4 * 4 + 3]);
                    *(float4*)(hb + q4 * 4) = v;
                }
            }
            grid_sync();
        }
    }

    // ================= projection =================
    const int gw = blockIdx.x * 8 + w;
    const int OUTHALF = Bsz * TAUn * Tt;
    for (int task = gw; task < TAUn * Bsz; task += GRID * 8) {
        const int t = task / Bsz;
        const int b = task % Bsz;
        const float* y = &g_y[((size_t)t * Bsz + b) << 10];
        float4 yv[8];
        #pragma unroll
        for (int q = 0; q < 8; q++)
            yv[q] = *(const float4*)&y[q * 128 + lane * 4];

        #pragma unroll
        for (int tt = 0; tt < Tt; tt++) {
            float d1 = 0.f, d2 = 0.f;
            #pragma unroll
            for (int q = 0; q < 8; q++) {
                const float4 w1 = *(const float4*)&W1[tt * Hd + q * 128 + lane * 4];
                const float4 w2 = *(const float4*)&W2[tt * Hd + q * 128 + lane * 4];
                d1 += yv[q].x * w1.x + yv[q].y * w1.y + yv[q].z * w1.z + yv[q].w * w1.w;
                d2 += yv[q].x * w2.x + yv[q].y * w2.y + yv[q].z * w2.z + yv[q].w * w2.w;
            }
            #pragma unroll
            for (int offs = 16; offs; offs >>= 1) {
                d1 += __shfl_down_sync(0xffffffffu, d1, offs);
                d2 += __shfl_down_sync(0xffffffffu, d2, offs);
            }
            if (lane == 0) {
                const float mu = d1 + b1[tt];
                const float z = 2.0f * (d2 + b2[tt]);   // BETA = 2
                const float sz = (z > 20.f) ? z : log1pf(__expf(z));
                out[((size_t)b * TAUn + t) * Tt + tt] = mu;
                out[OUTHALF + ((size_t)b * TAUn + t) * Tt + tt] = 0.5f * sz;
            }
        }
    }
}

extern "C" void kernel_launch(void* const* d_in, const int* in_sizes, int n_in,
                              void* d_out, int out_size) {
    (void)in_sizes; (void)n_in; (void)out_size;
    const float* hidden = (const float*)d_in[0];
    const float* cell   = (const float*)d_in[1];
    const float* W_ih   = (const float*)d_in[2];
    const float* W_hh   = (const float*)d_in[3];
    const float* b_ih   = (const float*)d_in[4];
    const float* b_hh   = (const float*)d_in[5];
    const float* W1     = (const float*)d_in[6];
    const float* b1     = (const float*)d_in[7];
    const float* W2     = (const float*)d_in[8];
    const float* b2     = (const float*)d_in[9];
    float* out = (float*)d_out;

    cudaFuncSetAttribute(deepar_mma,
                         cudaFuncAttributeMaxDynamicSharedMemorySize, SMEM_DYN);
    deepar_mma<<<GRID, NTH, SMEM_DYN>>>(hidden, cell, W_ih, W_hh, b_ih, b_hh,
                                        W1, b1, W2, b2, out);
}

// round 10
// speedup vs baseline: 1.0916x; 1.0916x over previous
#include <cuda_runtime.h>
#include <cstdint>

// Problem constants
#define Lnum 3
#define Bsz  512
#define Hd   1024
#define TAUn 96
#define Tt   8

#define GRID 128
#define NTH  512

// SMEM layout (byte offsets)
// 3 stages x (A 34816 + B 34816) = 208896 ; gates ALIASED onto stage region
#define STG   69632
#define ST_A(buf) ((buf) * STG)
#define ST_B(buf) ((buf) * STG + 34816)
#define OFF_GATES 0          // alias: gates live in stage region (dead at epilogue)
#define OFF_BIAS  208896     // 1536
#define SMEM_DYN  210432

#define APITCH 68            // floats per staged row (64 data + 4 pad); 68%32==4 -> conflict-free
#define GPITCH 36
#define GSTRIDE (128 * GPITCH)

// Persistent device state (canonical layouts only)
__device__ __align__(16) float g_wT[(size_t)2 * Lnum * 4096 * 1024]; // rounded [Wih; Whh]
__device__ __align__(16) float g_h[(size_t)2 * Lnum * Bsz * Hd];     // ping-pong hidden (rounded)
__device__ __align__(16) float g_y[(size_t)TAUn * Bsz * Hd];         // exact step outputs
__device__ unsigned int g_bar;                                       // ticket barrier

// ---------------------------------------------------------------- helpers
__device__ __forceinline__ uint32_t smem_u32(const void* p) {
    uint32_t a;
    asm("{ .reg .u64 t; cvta.to.shared.u64 t, %1; cvt.u32.u64 %0, t; }" : "=r"(a) : "l"(p));
    return a;
}
__device__ __forceinline__ float tf32r(float x) {
    uint32_t u;
    asm("cvt.rna.tf32.f32 %0, %1;" : "=r"(u) : "f"(x));
    return __uint_as_float(u);
}
__device__ __forceinline__ float4 cvt4(float4 v) {
    v.x = tf32r(v.x); v.y = tf32r(v.y); v.z = tf32r(v.z); v.w = tf32r(v.w);
    return v;
}
__device__ __forceinline__ float sigmoidf_(float x) { return 1.0f / (1.0f + __expf(-x)); }
__device__ __forceinline__ float tanhf_(float x) {
    float e = __expf(2.0f * x);
    return 1.0f - 2.0f / (e + 1.0f);
}

#define CP16(dst32, src) \
    asm volatile("cp.async.cg.shared.global [%0], [%1], 16;" :: "r"(dst32), "l"(src) : "memory")
#define CP_COMMIT()  asm volatile("cp.async.commit_group;" ::: "memory")
#define CP_WAIT1()   asm volatile("cp.async.wait_group 1;" ::: "memory")

__device__ __forceinline__ void mma_tf32(float& d0, float& d1, float& d2, float& d3,
                                         float a0, float a1, float a2, float a3,
                                         float b0, float b1) {
    asm volatile("mma.sync.aligned.m16n8k8.row.col.f32.tf32.tf32.f32 "
                 "{%0,%1,%2,%3}, {%4,%5,%6,%7}, {%8,%9}, {%0,%1,%2,%3};"
                 : "+f"(d0), "+f"(d1), "+f"(d2), "+f"(d3)
                 : "r"(__float_as_uint(a0)), "r"(__float_as_uint(a1)),
                   "r"(__float_as_uint(a2)), "r"(__float_as_uint(a3)),
                   "r"(__float_as_uint(b0)), "r"(__float_as_uint(b1)));
}

__device__ __forceinline__ void grid_sync() {
    __syncthreads();
    if (threadIdx.x == 0) {
        __threadfence();
        unsigned int ticket = atomicAdd(&g_bar, 1u);
        unsigned int target = ticket - (ticket % GRID) + GRID;
        volatile unsigned int* p = &g_bar;
        while ((int)(*p - target) < 0) { }
        __threadfence();
    }
    __syncthreads();
}

// ---------------------------------------------------------------- kernel
__global__ void __launch_bounds__(NTH, 1)
deepar_mma(const float* __restrict__ hidden,
           const float* __restrict__ cell,
           const float* __restrict__ W_ih,
           const float* __restrict__ W_hh,
           const float* __restrict__ b_ih,
           const float* __restrict__ b_hh,
           const float* __restrict__ W1,
           const float* __restrict__ b1,
           const float* __restrict__ W2,
           const float* __restrict__ b2,
           float* __restrict__ out)
{
    extern __shared__ __align__(16) char smb[];
    const uint32_t sb32 = smem_u32(smb);

    const int tid  = threadIdx.x;
    const int w    = tid >> 5;          // 0..15
    const int lane = tid & 31;
    const int wm   = w >> 2;            // 0..3  (M 32-row slice)
    const int wn   = w & 3;             // 0..3  (gate)
    const int g_   = lane >> 2;         // groupID
    const int t_   = lane & 3;          // threadID_in_group
    const int bt = blockIdx.x >> 5;     // 0..3  batch tile (128 rows)
    const int nt = blockIdx.x & 31;     // 0..31 hidden tile (32 cols)
    const int b0 = bt * 128;
    const int j0 = nt * 32;

    float* gatesS = (float*)(smb + OFF_GATES);   // aliased on stage region
    float* biasS  = (float*)(smb + OFF_BIAS);

    // ================= one-time precompute (elementwise only) =================
    {
        const int gt = blockIdx.x * NTH + tid;
        const float4* s1 = (const float4*)W_ih;
        const float4* s2 = (const float4*)W_hh;
        float4* d = (float4*)g_wT;
        const int PER = 3 * 4096 * 256;          // float4 per weight tensor
        for (int v = gt; v < PER; v += GRID * NTH) {
            d[v]       = cvt4(s1[v]);
            d[v + PER] = cvt4(s2[v]);
        }
        const float4* hs = (const float4*)hidden;
        float4* hd = (float4*)g_h;               // ping 0
        const int PH = 3 * 512 * 256;
        for (int v = gt; v < PH; v += GRID * NTH)
            hd[v] = cvt4(hs[v]);
    }

    // per-CTA bias (exact fp32): biasS[l*128 + g*32 + jj]
    for (int idx = tid; idx < Lnum * 128; idx += NTH) {
        const int l = idx >> 7, r = idx & 127;
        const int gi = l * 4096 + ((r >> 5) << 10) + j0 + (r & 31);
        biasS[idx] = b_ih[gi] + b_hh[gi];
    }

    // per-thread cell state in registers: thread owns (m = tid>>2, 8 j's)
    const int ml = tid >> 2;            // 0..127
    const int jb8 = (tid & 3) << 3;     // 0,8,16,24
    float creg[Lnum][8];
    #pragma unroll
    for (int l = 0; l < Lnum; l++) {
        #pragma unroll
        for (int q4 = 0; q4 < 2; q4++) {
            float4 v = *(const float4*)&cell[((size_t)(l * Bsz + b0 + ml) << 10)
                                             + j0 + jb8 + q4 * 4];
            creg[l][q4 * 4 + 0] = v.x; creg[l][q4 * 4 + 1] = v.y;
            creg[l][q4 * 4 + 2] = v.z; creg[l][q4 * 4 + 3] = v.w;
        }
    }
    grid_sync();

    const uint32_t stage0 = sb32;

    // ================= main recurrence =================
    for (int t = 0; t < TAUn; t++) {
        const int p  = t & 1;
        const int np = 1 - p;
        #pragma unroll
        for (int l = 0; l < Lnum; l++) {
            // canonical A sources: [512 rows][1024 cols]
            const float* Xp = (l == 0)
                ? g_h + (((size_t)(p * 3 + 2) * Bsz) << 10)
                : g_h + (((size_t)(np * 3 + (l - 1)) * Bsz) << 10);
            const float* Hp = g_h + (((size_t)(p * 3 + l) * Bsz) << 10);
            const float* Wi = g_wT + ((size_t)l << 22);                      // l*4096*1024
            const float* Wh = g_wT + ((size_t)(3 + l) << 22);

            float acc[2][4][4];
            #pragma unroll
            for (int mt = 0; mt < 2; mt++)
                #pragma unroll
                for (int jb = 0; jb < 4; jb++)
                    #pragma unroll
                    for (int r = 0; r < 4; r++) acc[mt][jb][r] = 0.0f;

// K=64 chunk staging: A 2048 CP16 (32KB, 128 rows x 64k), B 2048 CP16 (32KB).
// cid_ in 0..2047: row_ = cid_>>4 (0..127), k16_ = cid_&15 (16B sub-chunk).
#define ISSUE(c_, buf_) do {                                                   \
            const int cc_ = (c_);                                              \
            const float* Ap_ = (cc_ < 16) ? Xp : Hp;                           \
            const float* Wp_ = (cc_ < 16) ? Wi : Wh;                           \
            const int kc_ = (cc_ & 15) * 64;                                   \
            const uint32_t dA_ = stage0 + ST_A(buf_);                          \
            const uint32_t dB_ = stage0 + ST_B(buf_);                          \
            _Pragma("unroll")                                                  \
            for (int h_ = 0; h_ < 4; h_++) {                                   \
                const int cid_ = tid + h_ * NTH;                               \
                const int row_ = cid_ >> 4, k16_ = cid_ & 15;                  \
                CP16(dA_ + row_ * 272 + k16_ * 16,                             \
                     Ap_ + ((size_t)(b0 + row_) << 10) + kc_ + k16_ * 4);      \
                const int gg_ = row_ >> 5, jj_ = row_ & 31;                    \
                CP16(dB_ + row_ * 272 + k16_ * 16,                             \
                     Wp_ + ((size_t)(gg_ * 1024 + j0 + jj_) << 10) + kc_ + k16_ * 4); \
            } } while (0)

            // 3-stage ring, prefetch distance 2, one sync per chunk.
            ISSUE(0, 0); CP_COMMIT();
            ISSUE(1, 1); CP_COMMIT();

            #pragma unroll 1
            for (int s = 0; s < 32; s++) {
                const int buf = s % 3;
                CP_WAIT1();
                __syncthreads();
                // Buffer (s+2)%3 was consumed at iteration s-1; the sync above
                // guarantees all warps finished reading it. Safe to refill.
                if (s + 2 < 32) { ISSUE(s + 2, (s + 2) % 3); }
                CP_COMMIT();   // dummy when nothing issued: keeps wait count exact

                const float* As = (const float*)(smb + ST_A(buf));
                const float* Bs = (const float*)(smb + ST_B(buf));
                #pragma unroll
                for (int ks = 0; ks < 8; ks++) {
                    float a[2][4];
                    #pragma unroll
                    for (int mt = 0; mt < 2; mt++) {
                        const float* Ar = As + (wm * 32 + mt * 16) * APITCH + ks * 8;
                        a[mt][0] = Ar[g_ * APITCH + t_];
                        a[mt][1] = Ar[(g_ + 8) * APITCH + t_];
                        a[mt][2] = Ar[g_ * APITCH + t_ + 4];
                        a[mt][3] = Ar[(g_ + 8) * APITCH + t_ + 4];
                    }
                    float b[4][2];
                    #pragma unroll
                    for (int jb = 0; jb < 4; jb++) {
                        const float* Br = Bs + (wn * 32 + jb * 8 + g_) * APITCH
                                        + ks * 8 + t_;
                        b[jb][0] = Br[0];
                        b[jb][1] = Br[4];
                    }
                    #pragma unroll
                    for (int mt = 0; mt < 2; mt++)
                        #pragma unroll
                        for (int jb = 0; jb < 4; jb++)
                            mma_tf32(acc[mt][jb][0], acc[mt][jb][1],
                                     acc[mt][jb][2], acc[mt][jb][3],
                                     a[mt][0], a[mt][1], a[mt][2], a[mt][3],
                                     b[jb][0], b[jb][1]);
                }
            }
#undef ISSUE

            // ---- epilogue: accums -> smem gate buffer (aliases stage region) ----
            __syncthreads();
            #pragma unroll
            for (int mt = 0; mt < 2; mt++) {
                const int mb2 = wm * 32 + mt * 16 + g_;
                #pragma unroll
                for (int jb = 0; jb < 4; jb++) {
                    const int jc = jb * 8 + (t_ << 1);
                    float* gp = gatesS + wn * GSTRIDE + mb2 * GPITCH + jc;
                    *(float2*)gp = make_float2(acc[mt][jb][0], acc[mt][jb][1]);
                    *(float2*)(gp + 8 * GPITCH) = make_float2(acc[mt][jb][2], acc[mt][jb][3]);
                }
            }
            __syncthreads();

            // ---- LSTM cell (thread owns (ml, jb8..+8)) ----
            float G[4][8];
            #pragma unroll
            for (int g = 0; g < 4; g++)
                #pragma unroll
                for (int q4 = 0; q4 < 2; q4++) {
                    float4 v = *(const float4*)(gatesS + g * GSTRIDE + ml * GPITCH
                                                + jb8 + q4 * 4);
                    G[g][q4 * 4 + 0] = v.x; G[g][q4 * 4 + 1] = v.y;
                    G[g][q4 * 4 + 2] = v.z; G[g][q4 * 4 + 3] = v.w;
                }
            float hn[8];
            #pragma unroll
            for (int q = 0; q < 8; q++) {
                const int bb = l * 128 + jb8 + q;
                const float gi = sigmoidf_(G[0][q] + biasS[bb]);
                const float gf = sigmoidf_(G[1][q] + biasS[bb + 32]);
                const float gg = tanhf_  (G[2][q] + biasS[bb + 64]);
                const float go = sigmoidf_(G[3][q] + biasS[bb + 96]);
                const float cn = gf * creg[l][q] + gi * gg;
                creg[l][q] = cn;
                hn[q] = go * tanhf_(cn);
            }
            if (l == Lnum - 1) {
                float* yb = g_y + (((size_t)t * Bsz + b0 + ml) << 10) + j0 + jb8;
                #pragma unroll
                for (int q4 = 0; q4 < 2; q4++)
                    *(float4*)(yb + q4 * 4) = make_float4(hn[q4*4], hn[q4*4+1],
                                                          hn[q4*4+2], hn[q4*4+3]);
            }
            // rounded h -> canonical g_h[np][l]
            {
                float* hb = g_h + (((size_t)(np * 3 + l) * Bsz + b0 + ml) << 10)
                          + j0 + jb8;
                #pragma unroll
                for (int q4 = 0; q4 < 2; q4++) {
                    float4 v;
                    v.x = tf32r(hn[q4 * 4 + 0]); v.y = tf32r(hn[q4 * 4 + 1]);
                    v.z = tf32r(hn[q4 * 4 + 2]); v.w = tf32r(hn[q4 * 4 + 3]);
                    *(float4*)(hb + q4 * 4) = v;
                }
            }
            grid_sync();
        }
    }

    // ================= projection =================
    const int gw = blockIdx.x * 16 + w;
    const int OUTHALF = Bsz * TAUn * Tt;
    for (int task = gw; task < TAUn * Bsz; task += GRID * 16) {
        const int t = task / Bsz;
        const int b = task % Bsz;
        const float* y = &g_y[((size_t)t * Bsz + b) << 10];
        float4 yv[8];
        #pragma unroll
        for (int q = 0; q < 8; q++)
            yv[q] = *(const float4*)&y[q * 128 + lane * 4];

        #pragma unroll
        for (int tt = 0; tt < Tt; tt++) {
            float d1 = 0.f, d2 = 0.f;
            #pragma unroll
            for (int q = 0; q < 8; q++) {
                const float4 w1 = *(const float4*)&W1[tt * Hd + q * 128 + lane * 4];
                const float4 w2 = *(const float4*)&W2[tt * Hd + q * 128 + lane * 4];
                d1 += yv[q].x * w1.x + yv[q].y * w1.y + yv[q].z * w1.z + yv[q].w * w1.w;
                d2 += yv[q].x * w2.x + yv[q].y * w2.y + yv[q].z * w2.z + yv[q].w * w2.w;
            }
            #pragma unroll
            for (int offs = 16; offs; offs >>= 1) {
                d1 += __shfl_down_sync(0xffffffffu, d1, offs);
                d2 += __shfl_down_sync(0xffffffffu, d2, offs);
            }
            if (lane == 0) {
                const float mu = d1 + b1[tt];
                const float z = 2.0f * (d2 + b2[tt]);   // BETA = 2
                const float sz = (z > 20.f) ? z : log1pf(__expf(z));
                out[((size_t)b * TAUn + t) * Tt + tt] = mu;
                out[OUTHALF + ((size_t)b * TAUn + t) * Tt + tt] = 0.5f * sz;
            }
        }
    }
}

extern "C" void kernel_launch(void* const* d_in, const int* in_sizes, int n_in,
                              void* d_out, int out_size) {
    (void)in_sizes; (void)n_in; (void)out_size;
    const float* hidden = (const float*)d_in[0];
    const float* cell   = (const float*)d_in[1];
    const float* W_ih   = (const float*)d_in[2];
    const float* W_hh   = (const float*)d_in[3];
    const float* b_ih   = (const float*)d_in[4];
    const float* b_hh   = (const float*)d_in[5];
    const float* W1     = (const float*)d_in[6];
    const float* b1     = (const float*)d_in[7];
    const float* W2     = (const float*)d_in[8];
    const float* b2     = (const float*)d_in[9];
    float* out = (float*)d_out;

    cudaFuncSetAttribute(deepar_mma,
                         cudaFuncAttributeMaxDynamicSharedMemorySize, SMEM_DYN);
    deepar_mma<<<GRID, NTH, SMEM_DYN>>>(hidden, cell, W_ih, W_hh, b_ih, b_hh,
                                        W1, b1, W2, b2, out);
}